// round 1
// baseline (speedup 1.0000x reference)
#include <cuda_runtime.h>
#include <math.h>

#define DIM 128
#define TILE 64
#define THREADS 256
#define XS_STRIDE 132   // 128 + 4 pad, float4-aligned rows
#define MAXN 1100000
#define MAXSEG 8192

// ---------------- scratch (no allocation allowed) ----------------
__device__ float g_gate[MAXN];        // g, then e
__device__ float g_segmax[MAXSEG];
__device__ float g_segsum[MAXSEG];
__device__ int   g_idx_is64;

// ---------------- helpers ----------------
__device__ __forceinline__ float silu_f(float a) {
    // a * sigmoid(a) = a / (1 + exp(-a)); fast intrinsics, ~1e-6 rel err
    return __fdividef(a, 1.0f + __expf(-a));
}

__device__ __forceinline__ void atomicMaxF(float* addr, float v) {
    int old = __float_as_int(*addr);
    while (__int_as_float(old) < v) {
        int prev = atomicCAS((int*)addr, old, __float_as_int(v));
        if (prev == old) break;
        old = prev;
    }
}

__device__ __forceinline__ int load_index(const void* idxp, int i, bool is64) {
    return is64 ? (int)((const long long*)idxp)[i] : ((const int*)idxp)[i];
}

// ---------------- index dtype detection ----------------
// View the buffer as int32[n] (always in-bounds for both dtypes).
// If the data is int64 (values < 2^31), every odd int32 position is a zero
// high word. If int32, positions near the end hold segment ids ~4095 != 0.
__global__ void detect_idx_kernel(const int* v, int n) {
    int p = n - 1 - (int)threadIdx.x;
    int nz = 0;
    if (p >= 0 && (p & 1) && v[p] != 0) nz = 1;
    int any = __syncthreads_or(nz);
    if (threadIdx.x == 0) g_idx_is64 = any ? 0 : 1;
}

// ---------------- init ----------------
__global__ void init_kernel(float* out, int out_n, int S) {
    int i = blockIdx.x * blockDim.x + threadIdx.x;
    int stride = gridDim.x * blockDim.x;
    for (int p = i; p < out_n; p += stride) out[p] = 0.0f;
    for (int p = i; p < S; p += stride) { g_segmax[p] = -3.0e38f; g_segsum[p] = 0.0f; }
}

// ---------------- pass 1: gate + segment max ----------------
__global__ __launch_bounds__(THREADS)
void gate_kernel(const float* __restrict__ x, const void* __restrict__ idxp,
                 const float* __restrict__ Wg1, const float* __restrict__ bg1,
                 const float* __restrict__ Wg2, const float* __restrict__ bg2,
                 int N) {
    extern __shared__ float sm[];
    float* sW  = sm;                       // 128*128
    float* sb1 = sW + DIM * DIM;           // 128
    float* sw2 = sb1 + DIM;                // 128
    float* sx  = sw2 + DIM;                // TILE * XS_STRIDE
    int*  sidx = (int*)(sx + TILE * XS_STRIDE);  // TILE

    const int tid = threadIdx.x;
    const bool is64 = (g_idx_is64 != 0);

    for (int p = tid; p < DIM * DIM / 4; p += THREADS)
        ((float4*)sW)[p] = ((const float4*)Wg1)[p];
    if (tid < DIM) { sb1[tid] = bg1[tid]; sw2[tid] = Wg2[tid]; }
    const float bg2v = bg2[0];
    __syncthreads();

    const int cg = tid & 31;     // column group (4 cols)
    const int ng = tid >> 5;     // node group (8 nodes)
    const int ntiles = (N + TILE - 1) / TILE;

    for (int tile = blockIdx.x; tile < ntiles; tile += gridDim.x) {
        const int base = tile * TILE;

        for (int q = tid; q < TILE * (DIM / 4); q += THREADS) {
            int n = q >> 5, kv = q & 31;
            int node = base + n;
            float4 v = (node < N) ? ((const float4*)x)[node * (DIM / 4) + kv]
                                  : make_float4(0.f, 0.f, 0.f, 0.f);
            *(float4*)&sx[n * XS_STRIDE + kv * 4] = v;
        }
        if (tid < TILE) {
            int node = base + tid;
            sidx[tid] = (node < N) ? load_index(idxp, node, is64) : -1;
        }
        __syncthreads();

        float acc[8][4];
        #pragma unroll
        for (int i = 0; i < 8; ++i)
            #pragma unroll
            for (int c = 0; c < 4; ++c) acc[i][c] = 0.0f;

        #pragma unroll 8
        for (int k = 0; k < DIM; ++k) {
            const float4 w = *(const float4*)&sW[k * DIM + cg * 4];
            #pragma unroll
            for (int i = 0; i < 8; ++i) {
                const float xv = sx[(ng * 8 + i) * XS_STRIDE + k];
                acc[i][0] = fmaf(xv, w.x, acc[i][0]);
                acc[i][1] = fmaf(xv, w.y, acc[i][1]);
                acc[i][2] = fmaf(xv, w.z, acc[i][2]);
                acc[i][3] = fmaf(xv, w.w, acc[i][3]);
            }
        }

        // silu + dot with Wg2, then warp reduction (warp ng owns nodes ng*8..ng*8+7)
        float partial[8];
        #pragma unroll
        for (int i = 0; i < 8; ++i) {
            float p = 0.0f;
            #pragma unroll
            for (int c = 0; c < 4; ++c) {
                float a = acc[i][c] + sb1[cg * 4 + c];
                p = fmaf(silu_f(a), sw2[cg * 4 + c], p);
            }
            #pragma unroll
            for (int off = 16; off; off >>= 1)
                p += __shfl_xor_sync(0xffffffffu, p, off);
            partial[i] = p;
        }

        if (cg == 0) {
            int cur = -2; float cmax = 0.0f;
            #pragma unroll
            for (int i = 0; i < 8; ++i) {
                int n = ng * 8 + i, node = base + n;
                if (node >= N) break;
                float g = partial[i] + bg2v;
                g_gate[node] = g;
                int id = sidx[n];
                if (id != cur) {
                    if (cur >= 0) atomicMaxF(&g_segmax[cur], cmax);
                    cur = id; cmax = g;
                } else {
                    cmax = fmaxf(cmax, g);
                }
            }
            if (cur >= 0) atomicMaxF(&g_segmax[cur], cmax);
        }
        __syncthreads();
    }
}

// ---------------- pass 2: e = exp(g - max), segment sum ----------------
__global__ void softmax_kernel(const void* __restrict__ idxp, int N) {
    const bool is64 = (g_idx_is64 != 0);
    int stride = gridDim.x * blockDim.x;
    for (int i = blockIdx.x * blockDim.x + threadIdx.x; i < N; i += stride) {
        int id = load_index(idxp, i, is64);
        float e = __expf(g_gate[i] - g_segmax[id]);
        g_gate[i] = e;
        bool done = false;
        unsigned m = __activemask();
        if (m == 0xffffffffu) {
            int id0 = __shfl_sync(m, id, 0);
            if (__all_sync(m, id == id0)) {
                float s = e;
                #pragma unroll
                for (int off = 16; off; off >>= 1)
                    s += __shfl_xor_sync(m, s, off);
                if ((threadIdx.x & 31) == 0) atomicAdd(&g_segsum[id0], s);
                done = true;
            }
        }
        if (!done) atomicAdd(&g_segsum[id], e);
    }
}

// ---------------- pass 3: h MLP + weighted scatter ----------------
__global__ __launch_bounds__(THREADS)
void agg_kernel(const float* __restrict__ x, const void* __restrict__ idxp,
                const float* __restrict__ Wn1, const float* __restrict__ bn1,
                const float* __restrict__ Wn2, const float* __restrict__ bn2,
                float* __restrict__ out, int N) {
    extern __shared__ float sm[];
    float* sW1 = sm;                       // 128*128
    float* sW2 = sW1 + DIM * DIM;          // 128*128
    float* sb1 = sW2 + DIM * DIM;          // 128
    float* sb2 = sb1 + DIM;                // 128
    float* sx  = sb2 + DIM;                // TILE*XS_STRIDE (x tile, then t tile)
    float* sattn = sx + TILE * XS_STRIDE;  // TILE
    int*  sidx = (int*)(sattn + TILE);     // TILE

    const int tid = threadIdx.x;
    const bool is64 = (g_idx_is64 != 0);

    for (int p = tid; p < DIM * DIM / 4; p += THREADS) {
        ((float4*)sW1)[p] = ((const float4*)Wn1)[p];
        ((float4*)sW2)[p] = ((const float4*)Wn2)[p];
    }
    if (tid < DIM) { sb1[tid] = bn1[tid]; sb2[tid] = bn2[tid]; }
    __syncthreads();

    const int cg = tid & 31;
    const int ng = tid >> 5;
    const int ntiles = (N + TILE - 1) / TILE;

    for (int tile = blockIdx.x; tile < ntiles; tile += gridDim.x) {
        const int base = tile * TILE;

        for (int q = tid; q < TILE * (DIM / 4); q += THREADS) {
            int n = q >> 5, kv = q & 31;
            int node = base + n;
            float4 v = (node < N) ? ((const float4*)x)[node * (DIM / 4) + kv]
                                  : make_float4(0.f, 0.f, 0.f, 0.f);
            *(float4*)&sx[n * XS_STRIDE + kv * 4] = v;
        }
        if (tid < TILE) {
            int node = base + tid;
            if (node < N) {
                int id = load_index(idxp, node, is64);
                sidx[tid] = id;
                sattn[tid] = __fdividef(g_gate[node], g_segsum[id]);
            } else {
                sidx[tid] = 0;
                sattn[tid] = 0.0f;
            }
        }
        __syncthreads();

        // GEMM 1: acc1 = x @ Wn1
        float acc[8][4];
        #pragma unroll
        for (int i = 0; i < 8; ++i)
            #pragma unroll
            for (int c = 0; c < 4; ++c) acc[i][c] = 0.0f;

        #pragma unroll 8
        for (int k = 0; k < DIM; ++k) {
            const float4 w = *(const float4*)&sW1[k * DIM + cg * 4];
            #pragma unroll
            for (int i = 0; i < 8; ++i) {
                const float xv = sx[(ng * 8 + i) * XS_STRIDE + k];
                acc[i][0] = fmaf(xv, w.x, acc[i][0]);
                acc[i][1] = fmaf(xv, w.y, acc[i][1]);
                acc[i][2] = fmaf(xv, w.z, acc[i][2]);
                acc[i][3] = fmaf(xv, w.w, acc[i][3]);
            }
        }
        __syncthreads();  // all reads of sx done

        // t = silu(acc1 + bn1) -> overwrite sx
        #pragma unroll
        for (int i = 0; i < 8; ++i) {
            float4 t;
            t.x = silu_f(acc[i][0] + sb1[cg * 4 + 0]);
            t.y = silu_f(acc[i][1] + sb1[cg * 4 + 1]);
            t.z = silu_f(acc[i][2] + sb1[cg * 4 + 2]);
            t.w = silu_f(acc[i][3] + sb1[cg * 4 + 3]);
            *(float4*)&sx[(ng * 8 + i) * XS_STRIDE + cg * 4] = t;
        }
        __syncthreads();

        // GEMM 2: acc2 = t @ Wn2
        #pragma unroll
        for (int i = 0; i < 8; ++i)
            #pragma unroll
            for (int c = 0; c < 4; ++c) acc[i][c] = 0.0f;

        #pragma unroll 8
        for (int k = 0; k < DIM; ++k) {
            const float4 w = *(const float4*)&sW2[k * DIM + cg * 4];
            #pragma unroll
            for (int i = 0; i < 8; ++i) {
                const float tv = sx[(ng * 8 + i) * XS_STRIDE + k];
                acc[i][0] = fmaf(tv, w.x, acc[i][0]);
                acc[i][1] = fmaf(tv, w.y, acc[i][1]);
                acc[i][2] = fmaf(tv, w.z, acc[i][2]);
                acc[i][3] = fmaf(tv, w.w, acc[i][3]);
            }
        }

        // epilogue: out[seg][c] += attn * (acc2 + bn2), run-compressed atomics
        {
            const int nb = ng * 8;
            int cur = sidx[nb];
            float r0 = 0.f, r1 = 0.f, r2 = 0.f, r3 = 0.f;
            const float b0 = sb2[cg * 4 + 0], b1 = sb2[cg * 4 + 1];
            const float b2 = sb2[cg * 4 + 2], b3 = sb2[cg * 4 + 3];
            #pragma unroll
            for (int i = 0; i < 8; ++i) {
                int id = sidx[nb + i];
                float a = sattn[nb + i];
                if (id != cur) {
                    float* o = &out[cur * DIM + cg * 4];
                    atomicAdd(o + 0, r0); atomicAdd(o + 1, r1);
                    atomicAdd(o + 2, r2); atomicAdd(o + 3, r3);
                    r0 = r1 = r2 = r3 = 0.f;
                    cur = id;
                }
                r0 = fmaf(a, acc[i][0] + b0, r0);
                r1 = fmaf(a, acc[i][1] + b1, r1);
                r2 = fmaf(a, acc[i][2] + b2, r2);
                r3 = fmaf(a, acc[i][3] + b3, r3);
            }
            float* o = &out[cur * DIM + cg * 4];
            atomicAdd(o + 0, r0); atomicAdd(o + 1, r1);
            atomicAdd(o + 2, r2); atomicAdd(o + 3, r3);
        }
        __syncthreads();
    }
}

// ---------------- launch ----------------
extern "C" void kernel_launch(void* const* d_in, const int* in_sizes, int n_in,
                              void* d_out, int out_size) {
    const float* x   = (const float*)d_in[0];
    const void*  idx = d_in[1];
    // d_in[2] = dim_size scalar (unused; derived from out_size)
    const float* Wg1 = (const float*)d_in[3];
    const float* bg1 = (const float*)d_in[4];
    const float* Wg2 = (const float*)d_in[5];
    const float* bg2 = (const float*)d_in[6];
    const float* Wn1 = (const float*)d_in[7];
    const float* bn1 = (const float*)d_in[8];
    const float* Wn2 = (const float*)d_in[9];
    const float* bn2 = (const float*)d_in[10];
    float* out = (float*)d_out;

    const int N = in_sizes[0] / DIM;
    const int S = out_size / DIM;

    const size_t smem1 = (size_t)(DIM * DIM + DIM + DIM + TILE * XS_STRIDE) * 4 + TILE * 4;
    const size_t smem3 = (size_t)(2 * DIM * DIM + 2 * DIM + TILE * XS_STRIDE + TILE) * 4 + TILE * 4;

    cudaFuncSetAttribute(gate_kernel, cudaFuncAttributeMaxDynamicSharedMemorySize, (int)smem1);
    cudaFuncSetAttribute(agg_kernel,  cudaFuncAttributeMaxDynamicSharedMemorySize, (int)smem3);

    detect_idx_kernel<<<1, 256>>>((const int*)idx, N);
    init_kernel<<<256, 256>>>(out, out_size, S);

    gate_kernel<<<304, THREADS, smem1>>>(x, idx, Wg1, bg1, Wg2, bg2, N);

    int blocks2 = (N + 255) / 256;
    softmax_kernel<<<blocks2, 256>>>(idx, N);

    agg_kernel<<<152, THREADS, smem3>>>(x, idx, Wn1, bn1, Wn2, bn2, out, N);
}

// round 2
// speedup vs baseline: 1.8235x; 1.8235x over previous
#include <cuda_runtime.h>
#include <math.h>
#include <stdint.h>

#define DIM 128
#define TILE_M 256
#define THREADS 256
#define SROW 132            // padded row stride (floats): 132 % 32 == 4 -> conflict-free frag loads
#define MAXN 1100000
#define MAXSEG 8192

// ---------------- scratch ----------------
__device__ float g_gate[MAXN];        // g, then e
__device__ float g_segmax[MAXSEG];
__device__ float g_segsum[MAXSEG];
__device__ int   g_idx_is64;

// ---------------- helpers ----------------
__device__ __forceinline__ float silu_f(float a) {
    return __fdividef(a, 1.0f + __expf(-a));
}

__device__ __forceinline__ float to_tf32(float x) {
    uint32_t u;
    asm("cvt.rna.tf32.f32 %0, %1;" : "=r"(u) : "f"(x));
    return __uint_as_float(u);
}

__device__ __forceinline__ void atomicMaxF(float* addr, float v) {
    int old = __float_as_int(*addr);
    while (__int_as_float(old) < v) {
        int prev = atomicCAS((int*)addr, old, __float_as_int(v));
        if (prev == old) break;
        old = prev;
    }
}

__device__ __forceinline__ int load_index(const void* idxp, int i, bool is64) {
    return is64 ? (int)((const long long*)idxp)[i] : ((const int*)idxp)[i];
}

__device__ __forceinline__ void mma_tf32(float c[4], const uint32_t a[4], uint32_t b0, uint32_t b1) {
    asm volatile(
        "mma.sync.aligned.m16n8k8.row.col.f32.tf32.tf32.f32 "
        "{%0,%1,%2,%3}, {%4,%5,%6,%7}, {%8,%9}, {%0,%1,%2,%3};"
        : "+f"(c[0]), "+f"(c[1]), "+f"(c[2]), "+f"(c[3])
        : "r"(a[0]), "r"(a[1]), "r"(a[2]), "r"(a[3]), "r"(b0), "r"(b1));
}

// 256x128x128 tile GEMM: warp w owns rows [32w, 32w+32). acc[mi][j][c].
__device__ __forceinline__ void tile_gemm(const float* __restrict__ sx,
                                          const float* __restrict__ sW,
                                          float acc[2][16][4], int w, int lane) {
    const int ar = lane >> 2, ac = lane & 3;
    #pragma unroll
    for (int ks = 0; ks < 16; ++ks) {
        const int k0 = ks * 8;
        uint32_t a[2][4];
        #pragma unroll
        for (int mi = 0; mi < 2; ++mi) {
            const float* xb = sx + (w * 32 + mi * 16 + ar) * SROW + k0 + ac;
            a[mi][0] = __float_as_uint(xb[0]);
            a[mi][1] = __float_as_uint(xb[8 * SROW]);
            a[mi][2] = __float_as_uint(xb[4]);
            a[mi][3] = __float_as_uint(xb[8 * SROW + 4]);
        }
        const float* wb = sW + (k0 + ac) * SROW + ar;
        #pragma unroll
        for (int j = 0; j < 16; ++j) {
            uint32_t b0 = __float_as_uint(wb[j * 8]);
            uint32_t b1 = __float_as_uint(wb[4 * SROW + j * 8]);
            mma_tf32(acc[0][j], a[0], b0, b1);
            mma_tf32(acc[1][j], a[1], b0, b1);
        }
    }
}

__device__ __forceinline__ void zero_acc(float acc[2][16][4]) {
    #pragma unroll
    for (int mi = 0; mi < 2; ++mi)
        #pragma unroll
        for (int j = 0; j < 16; ++j)
            #pragma unroll
            for (int c = 0; c < 4; ++c) acc[mi][j][c] = 0.0f;
}

// ---------------- index dtype detection ----------------
__global__ void detect_idx_kernel(const int* v, int n) {
    int p = n - 1 - (int)threadIdx.x;
    int nz = 0;
    if (p >= 0 && (p & 1) && v[p] != 0) nz = 1;
    int any = __syncthreads_or(nz);
    if (threadIdx.x == 0) g_idx_is64 = any ? 0 : 1;
}

// ---------------- init ----------------
__global__ void init_kernel(float* out, int out_n, int S) {
    int i = blockIdx.x * blockDim.x + threadIdx.x;
    int stride = gridDim.x * blockDim.x;
    for (int p = i; p < out_n; p += stride) out[p] = 0.0f;
    for (int p = i; p < S; p += stride) { g_segmax[p] = -3.0e38f; g_segsum[p] = 0.0f; }
}

// ---------------- pass 1: gate GEMM (tf32 mma) + segment max ----------------
__global__ __launch_bounds__(THREADS)
void gate_kernel(const float* __restrict__ x, const void* __restrict__ idxp,
                 const float* __restrict__ Wg1, const float* __restrict__ bg1,
                 const float* __restrict__ Wg2, const float* __restrict__ bg2,
                 int N) {
    extern __shared__ float sm[];
    float* sW   = sm;                        // 128*SROW
    float* sx   = sW + DIM * SROW;           // 256*SROW
    float* sb1  = sx + TILE_M * SROW;        // 128
    float* sw2  = sb1 + DIM;                 // 128
    float* sg   = sw2 + DIM;                 // 256
    int*   sidx = (int*)(sg + TILE_M);       // 256

    const int tid = threadIdx.x;
    const int w = tid >> 5, lane = tid & 31;
    const int ar = lane >> 2, ac = lane & 3;
    const bool is64 = (g_idx_is64 != 0);

    // resident weights (tf32-rounded)
    for (int q = tid; q < DIM * (DIM / 4); q += THREADS) {
        int row = q >> 5, kv = q & 31;
        float4 v = ((const float4*)Wg1)[q];
        v.x = to_tf32(v.x); v.y = to_tf32(v.y); v.z = to_tf32(v.z); v.w = to_tf32(v.w);
        *(float4*)&sW[row * SROW + kv * 4] = v;
    }
    if (tid < DIM) { sb1[tid] = bg1[tid]; sw2[tid] = Wg2[tid]; }
    const float bg2v = bg2[0];
    __syncthreads();

    const int ntiles = (N + TILE_M - 1) / TILE_M;
    for (int tile = blockIdx.x; tile < ntiles; tile += gridDim.x) {
        const int base = tile * TILE_M;

        // load x tile (tf32-rounded) + indices
        for (int q = tid; q < TILE_M * (DIM / 4); q += THREADS) {
            int n = q >> 5, kv = q & 31;
            int node = base + n;
            float4 v = (node < N) ? ((const float4*)x)[(size_t)node * (DIM / 4) + kv]
                                  : make_float4(0.f, 0.f, 0.f, 0.f);
            v.x = to_tf32(v.x); v.y = to_tf32(v.y); v.z = to_tf32(v.z); v.w = to_tf32(v.w);
            *(float4*)&sx[n * SROW + kv * 4] = v;
        }
        if (tid < TILE_M) {
            int node = base + tid;
            sidx[tid] = (node < N) ? load_index(idxp, node, is64) : -1;
        }
        __syncthreads();

        float acc[2][16][4];
        zero_acc(acc);
        tile_gemm(sx, sW, acc, w, lane);

        // epilogue: g = silu(acc + b1) . w2 + b2, per-row reduce over quad
        #pragma unroll
        for (int mi = 0; mi < 2; ++mi) {
            #pragma unroll
            for (int rh = 0; rh < 2; ++rh) {
                float p = 0.0f;
                #pragma unroll
                for (int j = 0; j < 16; ++j) {
                    int c0 = 8 * j + 2 * ac;
                    p = fmaf(silu_f(acc[mi][j][2 * rh + 0] + sb1[c0]),     sw2[c0],     p);
                    p = fmaf(silu_f(acc[mi][j][2 * rh + 1] + sb1[c0 + 1]), sw2[c0 + 1], p);
                }
                p += __shfl_xor_sync(0xffffffffu, p, 1);
                p += __shfl_xor_sync(0xffffffffu, p, 2);
                if (ac == 0) {
                    int rl = w * 32 + mi * 16 + rh * 8 + ar;
                    float g = p + bg2v;
                    sg[rl] = g;
                    int node = base + rl;
                    if (node < N) g_gate[node] = g;
                }
            }
        }
        __syncwarp();

        // segmented max over this warp's 32 rows (sorted index -> contiguous runs)
        {
            int r = w * 32 + lane;
            int id = sidx[r];
            float v = (id >= 0) ? sg[r] : -3.0e38f;
            #pragma unroll
            for (int off = 1; off < 32; off <<= 1) {
                float ov = __shfl_down_sync(0xffffffffu, v, off);
                int  oid = __shfl_down_sync(0xffffffffu, id, off);
                if (lane + off < 32 && oid == id) v = fmaxf(v, ov);
            }
            int pid = __shfl_up_sync(0xffffffffu, id, 1);
            bool head = (lane == 0) || (pid != id);
            if (head && id >= 0) atomicMaxF(&g_segmax[id], v);
        }
        __syncthreads();
    }
}

// ---------------- pass 2: e = exp(g - max), segment sum ----------------
__global__ void softmax_kernel(const void* __restrict__ idxp, int N) {
    const bool is64 = (g_idx_is64 != 0);
    int stride = gridDim.x * blockDim.x;
    for (int i = blockIdx.x * blockDim.x + threadIdx.x; i < N; i += stride) {
        int id = load_index(idxp, i, is64);
        float e = __expf(g_gate[i] - g_segmax[id]);
        g_gate[i] = e;
        bool done = false;
        unsigned m = __activemask();
        if (m == 0xffffffffu) {
            int id0 = __shfl_sync(m, id, 0);
            if (__all_sync(m, id == id0)) {
                float s = e;
                #pragma unroll
                for (int off = 16; off; off >>= 1)
                    s += __shfl_xor_sync(m, s, off);
                if ((threadIdx.x & 31) == 0) atomicAdd(&g_segsum[id0], s);
                done = true;
            }
        }
        if (!done) atomicAdd(&g_segsum[id], e);
    }
}

// ---------------- pass 3: node MLP (tf32 mma x2) + weighted scatter ----------------
__global__ __launch_bounds__(THREADS)
void agg_kernel(const float* __restrict__ x, const void* __restrict__ idxp,
                const float* __restrict__ Wn1, const float* __restrict__ bn1,
                const float* __restrict__ Wn2, const float* __restrict__ bn2,
                float* __restrict__ out, int N) {
    extern __shared__ float sm[];
    float* sW    = sm;                        // 128*SROW  (W1 then W2)
    float* sx    = sW + DIM * SROW;           // 256*SROW  (x -> t -> scaled h)
    float* sb1   = sx + TILE_M * SROW;        // 128
    float* sb2   = sb1 + DIM;                 // 128
    float* sattn = sb2 + DIM;                 // 256
    int*   sidx  = (int*)(sattn + TILE_M);    // 256

    const int tid = threadIdx.x;
    const int w = tid >> 5, lane = tid & 31;
    const int ar = lane >> 2, ac = lane & 3;
    const bool is64 = (g_idx_is64 != 0);
    const int base = blockIdx.x * TILE_M;

    // W1 + biases
    for (int q = tid; q < DIM * (DIM / 4); q += THREADS) {
        int row = q >> 5, kv = q & 31;
        float4 v = ((const float4*)Wn1)[q];
        v.x = to_tf32(v.x); v.y = to_tf32(v.y); v.z = to_tf32(v.z); v.w = to_tf32(v.w);
        *(float4*)&sW[row * SROW + kv * 4] = v;
    }
    if (tid < DIM) { sb1[tid] = bn1[tid]; sb2[tid] = bn2[tid]; }

    // x tile + attn + idx
    for (int q = tid; q < TILE_M * (DIM / 4); q += THREADS) {
        int n = q >> 5, kv = q & 31;
        int node = base + n;
        float4 v = (node < N) ? ((const float4*)x)[(size_t)node * (DIM / 4) + kv]
                              : make_float4(0.f, 0.f, 0.f, 0.f);
        v.x = to_tf32(v.x); v.y = to_tf32(v.y); v.z = to_tf32(v.z); v.w = to_tf32(v.w);
        *(float4*)&sx[n * SROW + kv * 4] = v;
    }
    if (tid < TILE_M) {
        int node = base + tid;
        if (node < N) {
            int id = load_index(idxp, node, is64);
            sidx[tid] = id;
            sattn[tid] = __fdividef(g_gate[node], g_segsum[id]);
        } else {
            sidx[tid] = -1;
            sattn[tid] = 0.0f;
        }
    }
    __syncthreads();

    // GEMM 1: x @ W1
    float acc[2][16][4];
    zero_acc(acc);
    tile_gemm(sx, sW, acc, w, lane);

    // t = silu(acc + b1), tf32-rounded, back into own rows of sx (no cross-warp hazard)
    #pragma unroll
    for (int mi = 0; mi < 2; ++mi) {
        #pragma unroll
        for (int rh = 0; rh < 2; ++rh) {
            int row = w * 32 + mi * 16 + rh * 8 + ar;
            #pragma unroll
            for (int j = 0; j < 16; ++j) {
                int c0 = 8 * j + 2 * ac;
                float2 t;
                t.x = to_tf32(silu_f(acc[mi][j][2 * rh + 0] + sb1[c0]));
                t.y = to_tf32(silu_f(acc[mi][j][2 * rh + 1] + sb1[c0 + 1]));
                *(float2*)&sx[row * SROW + c0] = t;
            }
        }
    }
    __syncthreads();   // all warps done reading W1

    // swap in W2
    for (int q = tid; q < DIM * (DIM / 4); q += THREADS) {
        int row = q >> 5, kv = q & 31;
        float4 v = ((const float4*)Wn2)[q];
        v.x = to_tf32(v.x); v.y = to_tf32(v.y); v.z = to_tf32(v.z); v.w = to_tf32(v.w);
        *(float4*)&sW[row * SROW + kv * 4] = v;
    }
    __syncthreads();

    // GEMM 2: t @ W2
    zero_acc(acc);
    tile_gemm(sx, sW, acc, w, lane);

    // scaled h back into own rows of sx
    #pragma unroll
    for (int mi = 0; mi < 2; ++mi) {
        #pragma unroll
        for (int rh = 0; rh < 2; ++rh) {
            int row = w * 32 + mi * 16 + rh * 8 + ar;
            float a = sattn[row];
            #pragma unroll
            for (int j = 0; j < 16; ++j) {
                int c0 = 8 * j + 2 * ac;
                float2 t;
                t.x = a * (acc[mi][j][2 * rh + 0] + sb2[c0]);
                t.y = a * (acc[mi][j][2 * rh + 1] + sb2[c0 + 1]);
                *(float2*)&sx[row * SROW + c0] = t;
            }
        }
    }
    __syncthreads();

    // segmented column sums -> atomics (index sorted: ~1-3 runs per 128 rows)
    {
        int col = tid & 127;
        int r0 = (tid >> 7) * 128;
        float s = 0.0f;
        int cur = sidx[r0];
        #pragma unroll 4
        for (int r = r0; r < r0 + 128; ++r) {
            int id = sidx[r];
            float v = sx[r * SROW + col];
            if (id != cur) {
                if (cur >= 0) atomicAdd(&out[cur * DIM + col], s);
                s = 0.0f;
                cur = id;
            }
            s += v;
        }
        if (cur >= 0) atomicAdd(&out[cur * DIM + col], s);
    }
}

// ---------------- launch ----------------
extern "C" void kernel_launch(void* const* d_in, const int* in_sizes, int n_in,
                              void* d_out, int out_size) {
    const float* x   = (const float*)d_in[0];
    const void*  idx = d_in[1];
    const float* Wg1 = (const float*)d_in[3];
    const float* bg1 = (const float*)d_in[4];
    const float* Wg2 = (const float*)d_in[5];
    const float* bg2 = (const float*)d_in[6];
    const float* Wn1 = (const float*)d_in[7];
    const float* bn1 = (const float*)d_in[8];
    const float* Wn2 = (const float*)d_in[9];
    const float* bn2 = (const float*)d_in[10];
    float* out = (float*)d_out;

    const int N = in_sizes[0] / DIM;
    const int S = out_size / DIM;
    const int ntiles = (N + TILE_M - 1) / TILE_M;

    // smem: W(128*132) + tile(256*132) + 2*128 + 256 floats + 256 ints
    const size_t smem = (size_t)(DIM * SROW + TILE_M * SROW + 2 * DIM + TILE_M) * 4 + TILE_M * 4;

    cudaFuncSetAttribute(gate_kernel, cudaFuncAttributeMaxDynamicSharedMemorySize, (int)smem);
    cudaFuncSetAttribute(agg_kernel,  cudaFuncAttributeMaxDynamicSharedMemorySize, (int)smem);

    detect_idx_kernel<<<1, 256>>>((const int*)idx, N);
    init_kernel<<<256, 256>>>(out, out_size, S);

    gate_kernel<<<152, THREADS, smem>>>(x, idx, Wg1, bg1, Wg2, bg2, N);

    int blocks2 = (N + 255) / 256;
    softmax_kernel<<<blocks2, 256>>>(idx, N);

    agg_kernel<<<ntiles, THREADS, smem>>>(x, idx, Wn1, bn1, Wn2, bn2, out, N);
}